// round 2
// baseline (speedup 1.0000x reference)
#include <cuda_runtime.h>

// APMLSparse: x[B,N,3], y[B,M,3] fp32 -> scalar loss
// B=4, N=M=4096, D=3 (fixed shapes from metadata).
//
// Per row: d_j = sqrt(max(||x_n - y_j||^2, 1e-12)), e_j = exp(-d_j), Z = sum e_j.
// Kept set = elements in d-ascending order while exclusive prefix mass < 0.8*Z
// (including the crossing entry). loss += sum_kept e_j*d_j / Z.
//
// Strategy: 256-thread CTA processes RPC=8 rows of one batch. Each thread holds
// 16 y-points in registers (reused across the 8 rows). Exp-mass histogram
// (1024 bins over d in [0,16)) + block scan finds the crossing bin exactly;
// elements of the crossing bin get exact rank resolution in a small shared list.

#define NB      1024
#define BIN_SC  64.0f       // NB / 16
#define CAP     512
#define NTHREADS 256
#define RPC     8
#define MPTS    4096
#define NPT     16          // MPTS / NTHREADS

__global__ void apml_zero_out(float* o) { o[0] = 0.0f; }

__global__ __launch_bounds__(NTHREADS, 2)
void apml_kernel(const float* __restrict__ x, const float* __restrict__ y,
                 float* __restrict__ out)
{
    __shared__ float hist[NB];
    __shared__ float warpSum[8];
    __shared__ float redBuf[8];
    __shared__ float listD[CAP];
    __shared__ float listE[CAP];
    __shared__ int   s_cnt;
    __shared__ int   s_bb;
    __shared__ float s_cumBelow;
    __shared__ float s_Z;

    const int tid  = threadIdx.x;
    const int lane = tid & 31;
    const int wid  = tid >> 5;

    const int chunksPerBatch = 4096 / RPC;          // 512
    const int b       = blockIdx.x / chunksPerBatch;
    const int rowBase = (blockIdx.x % chunksPerBatch) * RPC;

    // Load this thread's 16 y points into registers (shared by all RPC rows).
    float yx[NPT], yy[NPT], yz[NPT];
    const float* yb = y + (size_t)b * MPTS * 3;
    #pragma unroll
    for (int k = 0; k < NPT; k++) {
        int j = k * NTHREADS + tid;
        yx[k] = yb[j * 3 + 0];
        yy[k] = yb[j * 3 + 1];
        yz[k] = yb[j * 3 + 2];
    }

    float ctaAcc = 0.0f;

    for (int r = 0; r < RPC; r++) {
        const int row = rowBase + r;
        const float* xp = x + ((size_t)b * 4096 + row) * 3;
        const float x0 = __ldg(xp + 0);
        const float x1 = __ldg(xp + 1);
        const float x2 = __ldg(xp + 2);

        // ---- zero histogram + list counter ----
        #pragma unroll
        for (int i = 0; i < NB / NTHREADS; i++) hist[tid + i * NTHREADS] = 0.0f;
        if (tid == 0) s_cnt = 0;
        __syncthreads();

        // ---- pass 1: distances, exp, histogram ----
        float dreg[NPT];
        #pragma unroll
        for (int k = 0; k < NPT; k++) {
            float dx = x0 - yx[k];
            float dy = x1 - yy[k];
            float dz = x2 - yz[k];
            float sq = fmaf(dx, dx, fmaf(dy, dy, dz * dz));
            sq = fmaxf(sq, 1e-12f);
            float d = sq * rsqrtf(sq);              // sqrt via MUFU.RSQ + mul
            dreg[k] = d;
            float e = __expf(-d);
            int bin = (int)(d * BIN_SC);
            bin = bin < (NB - 1) ? bin : (NB - 1);
            atomicAdd(&hist[bin], e);
        }
        __syncthreads();

        // ---- block scan of histogram (4 bins/thread) ----
        float h0 = hist[tid * 4 + 0];
        float h1 = hist[tid * 4 + 1];
        float h2 = hist[tid * 4 + 2];
        float h3 = hist[tid * 4 + 3];
        float tsum = h0 + h1 + h2 + h3;
        float v = tsum;
        #pragma unroll
        for (int off = 1; off < 32; off <<= 1) {
            float n = __shfl_up_sync(0xffffffffu, v, off);
            if (lane >= off) v += n;
        }
        if (lane == 31) warpSum[wid] = v;
        __syncthreads();
        if (tid == 0) {
            float run = 0.0f;
            #pragma unroll
            for (int i = 0; i < 8; i++) { float t = warpSum[i]; warpSum[i] = run; run += t; }
            s_Z = run;                               // Z = total histogram mass
        }
        __syncthreads();

        const float Z = s_Z;
        const float T = 0.8f * Z;
        // thread-exclusive prefix across block
        float cexcl = (v - tsum) + warpSum[wid];
        {
            float hh[4] = {h0, h1, h2, h3};
            #pragma unroll
            for (int j = 0; j < 4; j++) {
                float cincl = cexcl + hh[j];
                if (cexcl < T && cincl >= T) {       // unique crossing bin
                    s_bb = tid * 4 + j;
                    s_cumBelow = cexcl;
                }
                cexcl = cincl;
            }
        }
        __syncthreads();

        const int   bb       = s_bb;
        const float cumBelow = s_cumBelow;
        const float eThr     = 1e-10f * Z;           // p > THRESHOLD filter

        // ---- pass 2: sum kept bins, collect crossing-bin members ----
        float acc = 0.0f;
        #pragma unroll
        for (int k = 0; k < NPT; k++) {
            float d = dreg[k];
            int bin = (int)(d * BIN_SC);
            bin = bin < (NB - 1) ? bin : (NB - 1);
            if (bin <= bb) {
                float e = __expf(-d);
                if (bin < bb) {
                    if (e > eThr) acc = fmaf(e, d, acc);
                } else {
                    int idx = atomicAdd(&s_cnt, 1);
                    if (idx < CAP) { listD[idx] = d; listE[idx] = e; }
                    else           acc = fmaf(e, d, acc);   // overflow fallback
                }
            }
        }
        __syncthreads();

        // ---- exact rank resolution inside the crossing bin ----
        const int cnt = s_cnt < CAP ? s_cnt : CAP;
        const float Trem = T - cumBelow;
        for (int i = tid; i < cnt; i += NTHREADS) {
            float di = listD[i];
            float ei = listE[i];
            float rmass = 0.0f;
            for (int jj = 0; jj < cnt; jj++) {
                float dj = listD[jj];
                bool sm = (dj < di) || (dj == di && jj < i);
                rmass += sm ? listE[jj] : 0.0f;
            }
            if (rmass < Trem && ei > eThr) acc = fmaf(ei, di, acc);
        }

        // ---- block reduce row contribution ----
        #pragma unroll
        for (int off = 16; off; off >>= 1)
            acc += __shfl_xor_sync(0xffffffffu, acc, off);
        if (lane == 0) redBuf[wid] = acc;
        __syncthreads();
        if (tid == 0) {
            float tot = 0.0f;
            #pragma unroll
            for (int i = 0; i < 8; i++) tot += redBuf[i];
            ctaAcc += tot / Z;
        }
        __syncthreads();   // protect smem before next row's zeroing
    }

    if (tid == 0) atomicAdd(out, ctaAcc);
}

extern "C" void kernel_launch(void* const* d_in, const int* in_sizes, int n_in,
                              void* d_out, int out_size)
{
    const float* x = (const float*)d_in[0];
    const float* y = (const float*)d_in[1];
    float* out = (float*)d_out;

    apml_zero_out<<<1, 1>>>(out);
    const int grid = (4 * 4096) / RPC;   // 2048 CTAs
    apml_kernel<<<grid, NTHREADS>>>(x, y, out);
}